// round 16
// baseline (speedup 1.0000x reference)
#include <cuda_runtime.h>
#include <cuda_fp16.h>
#include <cstdint>

#define SS 512
#define BB 256
#define II 64
#define HH 512
#define G4 2048
#define NCTA 128

// ---------------- static device scratch (no allocs allowed) ----------------
__device__ float   g_xw[(size_t)SS * BB * G4];      // current-layer input projection (fp32)
__device__ __half  g_h1_hi[(size_t)SS * BB * HH], g_h1_lo[(size_t)SS * BB * HH];
__device__ __half  g_h2_hi[(size_t)SS * BB * HH], g_h2_lo[(size_t)SS * BB * HH];
__device__ __half  g_h3_hi[(size_t)SS * BB * HH], g_h3_lo[(size_t)SS * BB * HH];
__device__ __half  g_x_hi[(size_t)SS * BB * II],  g_x_lo[(size_t)SS * BB * II];

__device__ __half g_wih1_hi[G4 * II], g_wih1_lo[G4 * II];
__device__ __half g_whh1_hi[G4 * HH], g_whh1_lo[G4 * HH];
__device__ __half g_wih2_hi[G4 * HH], g_wih2_lo[G4 * HH];
__device__ __half g_whh2_hi[G4 * HH], g_whh2_lo[G4 * HH];
__device__ __half g_wih3_hi[G4 * HH], g_wih3_lo[G4 * HH];
__device__ __half g_whh3_hi[G4 * HH], g_whh3_lo[G4 * HH];

// leader-based group barriers (proven): 4 groups, each on its own 128B line
__device__ unsigned g_bcnt[4 * 32];
__device__ unsigned g_bgen[4 * 32];

// k-permutation within each 16-block: stored position q holds logical l16(q)
__device__ __forceinline__ int l16(int q) {
    return ((q >> 2) << 1) | (q & 1) | ((q & 2) << 2);
}

// ---------------- helpers ----------------
__device__ __forceinline__ void split_f16(float v, __half& hi, __half& lo) {
    hi = __float2half(v);
    lo = __float2half(v - __half2float(hi));
}

__device__ __forceinline__ void mma16816(float* d, const unsigned* a, const unsigned* b) {
    asm volatile(
        "mma.sync.aligned.m16n8k16.row.col.f32.f16.f16.f32 "
        "{%0,%1,%2,%3}, {%4,%5,%6,%7}, {%8,%9}, {%0,%1,%2,%3};\n"
        : "+f"(d[0]), "+f"(d[1]), "+f"(d[2]), "+f"(d[3])
        : "r"(a[0]), "r"(a[1]), "r"(a[2]), "r"(a[3]), "r"(b[0]), "r"(b[1]));
}

__device__ __forceinline__ unsigned smem_u32(const void* p) {
    unsigned a;
    asm("{ .reg .u64 t; cvta.to.shared.u64 t, %1; cvt.u32.u64 %0, t; }" : "=r"(a) : "l"(p));
    return a;
}

__device__ __forceinline__ void cp16(unsigned dst, const void* src) {
    asm volatile("cp.async.cg.shared.global [%0], [%1], 16;" :: "r"(dst), "l"(src));
}
__device__ __forceinline__ void cp_commit() {
    asm volatile("cp.async.commit_group;");
}
template <int N>
__device__ __forceinline__ void cp_wait() {
    asm volatile("cp.async.wait_group %0;" :: "n"(N));
}

__device__ __forceinline__ void bar_half(int half) {
    if (half == 0) asm volatile("bar.sync 1, 256;" ::: "memory");
    else           asm volatile("bar.sync 2, 256;" ::: "memory");
}

__device__ __forceinline__ float fsigmoid(float x) {
    return 1.f / (1.f + __expf(-x));
}
__device__ __forceinline__ float felu(float x) {
    return x > 0.f ? x : (__expf(x) - 1.f);
}

// leader-based group barrier: 32 CTAs of one batch group
__device__ __forceinline__ void gbar_g(unsigned target, int grp) {
    __syncthreads();
    if (threadIdx.x == 0) {
        unsigned* cnt = &g_bcnt[grp * 32];
        unsigned* gen = &g_bgen[grp * 32];
        __threadfence();
        if (atomicAdd(cnt, 1u) == 31u) {
            *cnt = 0;
            __threadfence();
            atomicExch(gen, target);
        } else {
            unsigned g;
            do {
                asm volatile("ld.global.acquire.gpu.u32 %0, [%1];" : "=r"(g) : "l"(gen));
            } while (g < target);
        }
    }
    __syncthreads();
}

__global__ void k_bar_init() {
    int i = threadIdx.x;
    if (i < 4 * 32) { g_bcnt[i] = 0; g_bgen[i] = 0; }
}

// ---------------- fused split kernel (weights + x), k-permuted, fp16 ----------------
#define NW1 (G4 * II)
#define NWH (G4 * HH)
#define NX  ((size_t)SS * BB * II)
#define NSPLIT (NW1 + 5 * NWH + NX)

__global__ void k_split_all(const float* __restrict__ x,
                            const float* __restrict__ wih1, const float* __restrict__ whh1,
                            const float* __restrict__ wih2, const float* __restrict__ whh2,
                            const float* __restrict__ wih3, const float* __restrict__ whh3) {
    size_t i = (size_t)blockIdx.x * 256 + threadIdx.x;
    if (i >= NSPLIT) return;
    if (i < NW1) {
        int j = (int)i;
        int p = j % II, row = j / II;
        int l = (p & ~15) | l16(p & 15);
        split_f16(wih1[row * II + l], g_wih1_hi[j], g_wih1_lo[j]);
    } else if (i < NW1 + 5 * (size_t)NWH) {
        size_t r = i - NW1;
        int t = (int)(r >> 20);              // NWH = 2^20
        int j = (int)(r & (NWH - 1));
        int p = j % HH, row = j / HH;
        int l = (p & ~15) | l16(p & 15);
        const float* src;
        __half *hi, *lo;
        switch (t) {
            case 0: src = whh1; hi = g_whh1_hi; lo = g_whh1_lo; break;
            case 1: src = wih2; hi = g_wih2_hi; lo = g_wih2_lo; break;
            case 2: src = whh2; hi = g_whh2_hi; lo = g_whh2_lo; break;
            case 3: src = wih3; hi = g_wih3_hi; lo = g_wih3_lo; break;
            default: src = whh3; hi = g_whh3_hi; lo = g_whh3_lo; break;
        }
        split_f16(src[(size_t)row * HH + l], hi[j], lo[j]);
    } else {
        size_t j = i - (NW1 + 5 * (size_t)NWH);
        int p = (int)(j % II);
        int b = (int)((j / II) % BB);
        int s = (int)(j / ((size_t)II * BB));
        int l = (p & ~15) | l16(p & 15);
        split_f16(x[((size_t)b * SS + s) * II + l], g_x_hi[j], g_x_lo[j]);
    }
}

// ---------------- layer-1 xw GEMM (K=64, 3-pass, proven body) ----------------
#define XBM 128
#define XBN 128
#define XBK 32
#define XST 4
#define XAP 40
#define X1_SMEM (XST * (XBM + XBN) * XAP * 2 * 2)   // 163840

__global__ __launch_bounds__(256) void k_gemm_x1(const float* __restrict__ bias) {
    const __half *Ah = g_x_hi, *Al = g_x_lo, *Wh = g_wih1_hi, *Wl = g_wih1_lo;
    const int K = II;

    extern __shared__ char xsm[];
    __half* sAh = (__half*)xsm;
    __half* sAl = sAh + XST * XBM * XAP;
    __half* sWh = sAl + XST * XBM * XAP;
    __half* sWl = sWh + XST * XBN * XAP;

    unsigned uAh = smem_u32(sAh), uAl = smem_u32(sAl);
    unsigned uWh = smem_u32(sWh), uWl = smem_u32(sWl);

    int tid = threadIdx.x;
    int m0 = blockIdx.y * XBM;
    int n0 = blockIdx.x * XBN;
    int warp = tid >> 5, lane = tid & 31;
    int wm = warp >> 1, wn = warp & 1;
    int gq = lane >> 2, tg = lane & 3;

    int lrow = tid >> 1;
    int lcol = (tid & 1) * 16;

    float acc[2][8][4];
#pragma unroll
    for (int mi = 0; mi < 2; mi++)
#pragma unroll
        for (int ni = 0; ni < 8; ni++)
#pragma unroll
            for (int r = 0; r < 4; r++) acc[mi][ni][r] = 0.f;

    int nkt = K / XBK;   // 2

    auto issue = [&](int kt, int st) {
        size_t ga = (size_t)(m0 + lrow) * K + kt * XBK + lcol;
        size_t gw = (size_t)(n0 + lrow) * K + kt * XBK + lcol;
        unsigned da = (unsigned)(((st * XBM + lrow) * XAP + lcol) * 2);
        unsigned dw = (unsigned)(((st * XBN + lrow) * XAP + lcol) * 2);
        cp16(uAh + da, Ah + ga);       cp16(uAh + da + 16, Ah + ga + 8);
        cp16(uAl + da, Al + ga);       cp16(uAl + da + 16, Al + ga + 8);
        cp16(uWh + dw, Wh + gw);       cp16(uWh + dw + 16, Wh + gw + 8);
        cp16(uWl + dw, Wl + gw);       cp16(uWl + dw + 16, Wl + gw + 8);
        cp_commit();
    };

    int npro = nkt < (XST - 1) ? nkt : (XST - 1);
    for (int p = 0; p < npro; p++) issue(p, p);

    for (int kt = 0; kt < nkt; kt++) {
        int rem = nkt - kt - 1;
        if (rem >= 2) cp_wait<2>();
        else if (rem == 1) cp_wait<1>();
        else cp_wait<0>();
        __syncthreads();

        if (kt + XST - 1 < nkt) issue(kt + XST - 1, (kt + XST - 1) % XST);

        int st = kt % XST;
        const __half* cAh = sAh + st * XBM * XAP;
        const __half* cAl = sAl + st * XBM * XAP;
        const __half* cWh = sWh + st * XBN * XAP;
        const __half* cWl = sWl + st * XBN * XAP;

#pragma unroll
        for (int kc = 0; kc < XBK; kc += 16) {
            unsigned ah[2][4], al[2][4], bh[8][2], bl[8][2];
#pragma unroll
            for (int mi = 0; mi < 2; mi++) {
                int r = wm * 32 + mi * 16 + gq;
                ah[mi][0] = *(unsigned*)&cAh[r * XAP + kc + 2 * tg];
                ah[mi][1] = *(unsigned*)&cAh[(r + 8) * XAP + kc + 2 * tg];
                ah[mi][2] = *(unsigned*)&cAh[r * XAP + kc + 2 * tg + 8];
                ah[mi][3] = *(unsigned*)&cAh[(r + 8) * XAP + kc + 2 * tg + 8];
                al[mi][0] = *(unsigned*)&cAl[r * XAP + kc + 2 * tg];
                al[mi][1] = *(unsigned*)&cAl[(r + 8) * XAP + kc + 2 * tg];
                al[mi][2] = *(unsigned*)&cAl[r * XAP + kc + 2 * tg + 8];
                al[mi][3] = *(unsigned*)&cAl[(r + 8) * XAP + kc + 2 * tg + 8];
            }
#pragma unroll
            for (int ni = 0; ni < 8; ni++) {
                int n = wn * 64 + ni * 8 + gq;
                bh[ni][0] = *(unsigned*)&cWh[n * XAP + kc + 2 * tg];
                bh[ni][1] = *(unsigned*)&cWh[n * XAP + kc + 2 * tg + 8];
                bl[ni][0] = *(unsigned*)&cWl[n * XAP + kc + 2 * tg];
                bl[ni][1] = *(unsigned*)&cWl[n * XAP + kc + 2 * tg + 8];
            }
#pragma unroll
            for (int mi = 0; mi < 2; mi++)
#pragma unroll
                for (int ni = 0; ni < 8; ni++) {
                    mma16816(acc[mi][ni], ah[mi], bh[ni]);
                    mma16816(acc[mi][ni], ah[mi], bl[ni]);
                    mma16816(acc[mi][ni], al[mi], bh[ni]);
                }
        }
    }

#pragma unroll
    for (int mi = 0; mi < 2; mi++)
#pragma unroll
        for (int ni = 0; ni < 8; ni++) {
            int row = m0 + wm * 32 + mi * 16 + gq;
            int col = n0 + wn * 64 + ni * 8 + 2 * tg;
            float b0v = bias[col], b1v = bias[col + 1];
            g_xw[(size_t)row * G4 + col]           = acc[mi][ni][0] + b0v;
            g_xw[(size_t)row * G4 + col + 1]       = acc[mi][ni][1] + b1v;
            g_xw[(size_t)(row + 8) * G4 + col]     = acc[mi][ni][2] + b0v;
            g_xw[(size_t)(row + 8) * G4 + col + 1] = acc[mi][ni][3] + b1v;
        }
}

// ---------------- xw GEMM for layers 2/3: A = h_hi (2-pass), K=512 ----------------
#define XH_SMEM (3 * XST * XBM * XAP * 2)   // 122880 (A, Wh, Wl)

__global__ __launch_bounds__(256) void k_gemm_h(int layer, const float* __restrict__ bias) {
    const __half *Ah, *Wh, *Wl;
    if (layer == 1) { Ah = g_h1_hi; Wh = g_wih2_hi; Wl = g_wih2_lo; }
    else            { Ah = g_h2_hi; Wh = g_wih3_hi; Wl = g_wih3_lo; }
    const int K = HH;

    extern __shared__ char xsm[];
    __half* sAh = (__half*)xsm;
    __half* sWh = sAh + XST * XBM * XAP;
    __half* sWl = sWh + XST * XBN * XAP;

    unsigned uAh = smem_u32(sAh), uWh = smem_u32(sWh), uWl = smem_u32(sWl);

    int tid = threadIdx.x;
    int m0 = blockIdx.y * XBM;
    int n0 = blockIdx.x * XBN;
    int warp = tid >> 5, lane = tid & 31;
    int wm = warp >> 1, wn = warp & 1;
    int gq = lane >> 2, tg = lane & 3;

    int lrow = tid >> 1;
    int lcol = (tid & 1) * 16;

    float acc[2][8][4];
#pragma unroll
    for (int mi = 0; mi < 2; mi++)
#pragma unroll
        for (int ni = 0; ni < 8; ni++)
#pragma unroll
            for (int r = 0; r < 4; r++) acc[mi][ni][r] = 0.f;

    int nkt = K / XBK;   // 16

    auto issue = [&](int kt, int st) {
        size_t ga = (size_t)(m0 + lrow) * K + kt * XBK + lcol;
        size_t gw = (size_t)(n0 + lrow) * K + kt * XBK + lcol;
        unsigned da = (unsigned)(((st * XBM + lrow) * XAP + lcol) * 2);
        cp16(uAh + da, Ah + ga);       cp16(uAh + da + 16, Ah + ga + 8);
        cp16(uWh + da, Wh + gw);       cp16(uWh + da + 16, Wh + gw + 8);
        cp16(uWl + da, Wl + gw);       cp16(uWl + da + 16, Wl + gw + 8);
        cp_commit();
    };

    for (int p = 0; p < XST - 1; p++) issue(p, p);

    for (int kt = 0; kt < nkt; kt++) {
        int rem = nkt - kt - 1;
        if (rem >= 2) cp_wait<2>();
        else if (rem == 1) cp_wait<1>();
        else cp_wait<0>();
        __syncthreads();

        if (kt + XST - 1 < nkt) issue(kt + XST - 1, (kt + XST - 1) % XST);

        int st = kt % XST;
        const __half* cAh = sAh + st * XBM * XAP;
        const __half* cWh = sWh + st * XBN * XAP;
        const __half* cWl = sWl + st * XBN * XAP;

#pragma unroll
        for (int kc = 0; kc < XBK; kc += 16) {
            unsigned ah[2][4], bh[8][2], bl[8][2];
#pragma unroll
            for (int mi = 0; mi < 2; mi++) {
                int r = wm * 32 + mi * 16 + gq;
                ah[mi][0] = *(unsigned*)&cAh[r * XAP + kc + 2 * tg];
                ah[mi][1] = *(unsigned*)&cAh[(r + 8) * XAP + kc + 2 * tg];
                ah[mi][2] = *(unsigned*)&cAh[r * XAP + kc + 2 * tg + 8];
                ah[mi][3] = *(unsigned*)&cAh[(r + 8) * XAP + kc + 2 * tg + 8];
            }
#pragma unroll
            for (int ni = 0; ni < 8; ni++) {
                int n = wn * 64 + ni * 8 + gq;
                bh[ni][0] = *(unsigned*)&cWh[n * XAP + kc + 2 * tg];
                bh[ni][1] = *(unsigned*)&cWh[n * XAP + kc + 2 * tg + 8];
                bl[ni][0] = *(unsigned*)&cWl[n * XAP + kc + 2 * tg];
                bl[ni][1] = *(unsigned*)&cWl[n * XAP + kc + 2 * tg + 8];
            }
#pragma unroll
            for (int mi = 0; mi < 2; mi++)
#pragma unroll
                for (int ni = 0; ni < 8; ni++) {
                    mma16816(acc[mi][ni], ah[mi], bh[ni]);
                    mma16816(acc[mi][ni], ah[mi], bl[ni]);
                }
        }
    }

#pragma unroll
    for (int mi = 0; mi < 2; mi++)
#pragma unroll
        for (int ni = 0; ni < 8; ni++) {
            int row = m0 + wm * 32 + mi * 16 + gq;
            int col = n0 + wn * 64 + ni * 8 + 2 * tg;
            float b0v = bias[col], b1v = bias[col + 1];
            g_xw[(size_t)row * G4 + col]           = acc[mi][ni][0] + b0v;
            g_xw[(size_t)row * G4 + col + 1]       = acc[mi][ni][1] + b1v;
            g_xw[(size_t)(row + 8) * G4 + col]     = acc[mi][ni][2] + b0v;
            g_xw[(size_t)(row + 8) * G4 + col + 1] = acc[mi][ni][3] + b1v;
        }
}

// ---------------- persistent recurrent kernel: split-K, fp16 2-pass, RKT=128 ----------
// 128 CTAs x 512 threads. Half h computes 64x64 tile over K[h*256, h*256+256),
// TWO serial k-tiles of 128 each, double-buffered, order: wait -> bar -> issue -> consume.
// SMEM (bytes):
//   0      sWh[64][528]                 67584
//   67584  sWl[64][528]                 67584   (ends 135168)
//   135168 half0 h bufs: 2 x 64x136x2 = 34816
//   169984 half1 h bufs: 2 x 64x136x2 = 34816
//   204800 red 64x68x4              =  17408   (ends 222208)
#define SMEM_REC 222208
#define SWP 528
#define STP 136
#define RKT 128
#define HBUFB 17408            // bytes per h buffer
#define HB_OFF 135168
#define RED_OFF 204800
#define REDP 68

__global__ __launch_bounds__(512, 1) void k_rec(int layer) {
    extern __shared__ char sm[];
    __half (*sWh)[SWP] = (__half(*)[SWP])(sm);
    __half (*sWl)[SWP] = (__half(*)[SWP])(sm + 67584);
    float* red = (float*)(sm + RED_OFF);

    const __half *Whg, *Wlg;
    __half *HOhi, *HOlo;
    if (layer == 0)      { Whg = g_whh1_hi; Wlg = g_whh1_lo; HOhi = g_h1_hi; HOlo = g_h1_lo; }
    else if (layer == 1) { Whg = g_whh2_hi; Wlg = g_whh2_lo; HOhi = g_h2_hi; HOlo = g_h2_lo; }
    else                 { Whg = g_whh3_hi; Wlg = g_whh3_lo; HOhi = g_h3_hi; HOlo = g_h3_lo; }

    int tid = threadIdx.x;
    int half = tid >> 8;
    int htid = tid & 255;
    int lane = tid & 31;
    int hw = htid >> 5;
    int bx = blockIdx.x;
    int bhid = bx >> 2;
    int bbat = bx & 3;
    int m0 = bbat * 64;
    int n0 = bhid * 16;
    int wm = hw >> 1, wn = hw & 1;
    int gq = lane >> 2, tg = lane & 3;
    int koff = half * 256;

    // resident W slice (hi+lo)
    for (int idx = tid; idx < 64 * 256; idx += 512) {
        int r = idx >> 8;
        int c = (idx & 255) * 2;
        int grow = (r >> 4) * HH + n0 + (r & 15);
        size_t gi = (size_t)grow * HH + c;
        *(unsigned*)&sWh[r][c] = *(const unsigned*)&Whg[gi];
        *(unsigned*)&sWl[r][c] = *(const unsigned*)&Wlg[gi];
    }
    __syncthreads();

    unsigned hb = smem_u32(sm) + HB_OFF + (unsigned)half * (2u * HBUFB);
    int lrow = htid >> 2;             // 64 rows, 4 threads/row
    int lcol = (htid & 3) * 32;       // 32 cols per thread: chunks +0,+8,+16,+24

    int row0 = wm * 16 + gq;
    int jloc = wn * 8 + 2 * tg;
    int jst  = 4 * tg + 2 * wn;

    unsigned base_t = (unsigned)layer * SS;

    float cb[2][2] = {{0.f, 0.f}, {0.f, 0.f}};
    float xwn[4][2][2];
    if (half == 0) {
        const float* xwb = g_xw + ((size_t)0 * BB + m0 + row0) * G4;
#pragma unroll
        for (int g = 0; g < 4; g++)
#pragma unroll
            for (int rr = 0; rr < 2; rr++) {
                float2 v = *(const float2*)(xwb + (size_t)rr * 8 * G4 + g * HH + n0 + jloc);
                xwn[g][rr][0] = v.x; xwn[g][rr][1] = v.y;
            }
    }

    for (int s = 0; s < SS; s++) {
        float acc[4][4];
#pragma unroll
        for (int g = 0; g < 4; g++)
#pragma unroll
            for (int r = 0; r < 4; r++) acc[g][r] = 0.f;

        if (s > 0) {
            const __half* Hh = HOhi + ((size_t)(s - 1) * BB + m0) * HH;

            auto issueH = [&](int kt) {
                int b = kt & 1;
                const __half* gh = Hh + (size_t)lrow * HH + koff + kt * RKT + lcol;
                unsigned d = (unsigned)(b * HBUFB + (lrow * STP + lcol) * 2);
#pragma unroll
                for (int q = 0; q < 4; q++)
                    cp16(hb + d + q * 16, gh + q * 8);
                cp_commit();
            };

            issueH(0);
#pragma unroll
            for (int kt = 0; kt < 2; kt++) {
                cp_wait<0>();                     // tile kt landed (this thread's copies)
                bar_half(half);                   // all threads' copies visible; prev buffer free
                if (kt == 0) issueH(1);

                int b = kt & 1;
                const __half* cHh = (const __half*)(sm + HB_OFF + half * (2 * HBUFB) + b * HBUFB);
#pragma unroll
                for (int kc = 0; kc < RKT; kc += 16) {
                    int kw = koff + kt * RKT + kc;
                    unsigned ah[4], bh[4][2], bl[4][2];
                    uint2 t;
                    t = *(uint2*)&cHh[row0 * STP + kc + 4 * tg];        ah[0] = t.x; ah[2] = t.y;
                    t = *(uint2*)&cHh[(row0 + 8) * STP + kc + 4 * tg];  ah[1] = t.x; ah[3] = t.y;
#pragma unroll
                    for (int g = 0; g < 4; g++) {
                        int n = g * 16 + wn * 8 + gq;
                        t = *(uint2*)&sWh[n][kw + 4 * tg];  bh[g][0] = t.x; bh[g][1] = t.y;
                        t = *(uint2*)&sWl[n][kw + 4 * tg];  bl[g][0] = t.x; bl[g][1] = t.y;
                    }
#pragma unroll
                    for (int g = 0; g < 4; g++) {
                        mma16816(acc[g], ah, bh[g]);
                        mma16816(acc[g], ah, bl[g]);
                    }
                }
            }
        }

        // ---- cross-half reduction ----
        __syncthreads();
        if (s > 0) {
            if (half == 1) {
#pragma unroll
                for (int g = 0; g < 4; g++)
#pragma unroll
                    for (int rr = 0; rr < 2; rr++)
#pragma unroll
                        for (int cc = 0; cc < 2; cc++)
                            red[(row0 + rr * 8) * REDP + g * 16 + jloc + cc] = acc[g][rr * 2 + cc];
            }
            __syncthreads();
            if (half == 0) {
#pragma unroll
                for (int g = 0; g < 4; g++)
#pragma unroll
                    for (int rr = 0; rr < 2; rr++)
#pragma unroll
                        for (int cc = 0; cc < 2; cc++)
                            acc[g][rr * 2 + cc] += red[(row0 + rr * 8) * REDP + g * 16 + jloc + cc];
            }
        }

        if (half == 0) {
            float xwf[4][2][2];
#pragma unroll
            for (int g = 0; g < 4; g++)
#pragma unroll
                for (int rr = 0; rr < 2; rr++) {
                    xwf[g][rr][0] = xwn[g][rr][0];
                    xwf[g][rr][1] = xwn[g][rr][1];
                }
            if (s + 1 < SS) {
                const float* xwb = g_xw + ((size_t)(s + 1) * BB + m0 + row0) * G4;
#pragma unroll
                for (int g = 0; g < 4; g++)
#pragma unroll
                    for (int rr = 0; rr < 2; rr++) {
                        float2 v = *(const float2*)(xwb + (size_t)rr * 8 * G4 + g * HH + n0 + jloc);
                        xwn[g][rr][0] = v.x; xwn[g][rr][1] = v.y;
                    }
            }

#pragma unroll
            for (int rr = 0; rr < 2; rr++) {
                __half hh[2], hl[2];
#pragma unroll
                for (int cc = 0; cc < 2; cc++) {
                    int fi = rr * 2 + cc;
                    float pi = acc[0][fi] + xwf[0][rr][cc];
                    float pf = acc[1][fi] + xwf[1][rr][cc];
                    float pg = acc[2][fi] + xwf[2][rr][cc];
                    float po = acc[3][fi] + xwf[3][rr][cc];
                    float iv = fsigmoid(pi);
                    float fv = fsigmoid(pf);
                    float gv = felu(pg);
                    float ov = fsigmoid(po);
                    float cn = fv * cb[rr][cc] + iv * gv;
                    float hv = ov * felu(cn);
                    cb[rr][cc] = cn;
                    split_f16(hv, hh[cc], hl[cc]);
                }
                size_t hidx = ((size_t)s * BB + m0 + row0 + rr * 8) * HH + n0 + jst;
                *(unsigned*)(HOhi + hidx) = *(unsigned*)hh;
                if (layer == 2)                     // lo consumed only by k_fc
                    *(unsigned*)(HOlo + hidx) = *(unsigned*)hl;
            }
        }

        gbar_g(base_t + (unsigned)s + 1u, bbat);
    }
}

// ---------------- final FC: out[b] = h3[S-1,b,:] . fc_w + fc_b (hi+lo, permuted) ----
__global__ void k_fc(const float* __restrict__ fcw, const float* __restrict__ fcb,
                     float* __restrict__ out) {
    __shared__ float red[4];
    int b = blockIdx.x, tid = threadIdx.x;
    size_t base = ((size_t)(SS - 1) * BB + b) * HH;
    float sum = 0.f;
    for (int p = tid; p < HH; p += 128) {
        int l = (p & ~15) | l16(p & 15);
        sum += (__half2float(g_h3_hi[base + p]) + __half2float(g_h3_lo[base + p])) * fcw[l];
    }
#pragma unroll
    for (int o = 16; o; o >>= 1) sum += __shfl_xor_sync(0xFFFFFFFFu, sum, o);
    if ((tid & 31) == 0) red[tid >> 5] = sum;
    __syncthreads();
    if (tid == 0) out[b] = red[0] + red[1] + red[2] + red[3] + fcb[0];
}

// ---------------- launch ----------------
extern "C" void kernel_launch(void* const* d_in, const int* in_sizes, int n_in,
                              void* d_out, int out_size) {
    const float* x    = (const float*)d_in[0];
    const float* wih1 = (const float*)d_in[1];
    const float* whh1 = (const float*)d_in[2];
    const float* b1   = (const float*)d_in[3];
    const float* wih2 = (const float*)d_in[4];
    const float* whh2 = (const float*)d_in[5];
    const float* b2   = (const float*)d_in[6];
    const float* wih3 = (const float*)d_in[7];
    const float* whh3 = (const float*)d_in[8];
    const float* b3   = (const float*)d_in[9];
    const float* fcw  = (const float*)d_in[10];
    const float* fcb  = (const float*)d_in[11];

    cudaFuncSetAttribute(k_rec, cudaFuncAttributeMaxDynamicSharedMemorySize, SMEM_REC);
    cudaFuncSetAttribute(k_gemm_x1, cudaFuncAttributeMaxDynamicSharedMemorySize, X1_SMEM);
    cudaFuncSetAttribute(k_gemm_h, cudaFuncAttributeMaxDynamicSharedMemorySize, XH_SMEM);

    // 0 split, 1 barinit, 2 gemm_x1, 3 rec0, 4 gemm_h, 5 rec1 (ncu -s 5), 6 gemm_h, 7 rec2, 8 fc
    size_t nsp = NSPLIT;
    k_split_all<<<(unsigned)((nsp + 255) / 256), 256>>>(x, wih1, whh1, wih2, whh2, wih3, whh3);
    k_bar_init<<<1, 128>>>();

    dim3 gg(G4 / XBN, (SS * BB) / XBM);
    k_gemm_x1<<<gg, 256, X1_SMEM>>>(b1);
    k_rec<<<NCTA, 512, SMEM_REC>>>(0);
    k_gemm_h<<<gg, 256, XH_SMEM>>>(1, b2);
    k_rec<<<NCTA, 512, SMEM_REC>>>(1);
    k_gemm_h<<<gg, 256, XH_SMEM>>>(2, b3);
    k_rec<<<NCTA, 512, SMEM_REC>>>(2);
    k_fc<<<BB, 128>>>(fcw, fcb, (float*)d_out);
}